// round 4
// baseline (speedup 1.0000x reference)
#include <cuda_runtime.h>
#include <cstdint>
#include <math.h>

// ---------------- problem constants ----------------
#define NTOK    32768          // B*T
#define NEXP    16
#define LINP    1792           // packed features (city folded into bias)
#define KC      16             // feature chunk
#define NCHUNK  112            // 1792/16
#define TPB     128
#define TOKBLK  64
#define NBLK    (NTOK / TOKBLK)   // 512

#define IDX_OFF (NTOK * NEXP)            // 524288
#define G1_OFF  (IDX_OFF + NTOK * 2)     // 589824

__device__ __align__(16) float2 g_wpack[LINP * NEXP];
__device__ float2 g_bias[NEXP];

// ---------------- helpers ----------------
__device__ __forceinline__ void fma2(unsigned long long& acc,
                                     unsigned long long x,
                                     unsigned long long w) {
    asm("fma.rn.f32x2 %0, %1, %2, %0;" : "+l"(acc) : "l"(x), "l"(w));
}
__device__ __forceinline__ unsigned long long pack2(float v) {
    unsigned long long r;
    asm("mov.b64 %0, {%1, %1};" : "=l"(r) : "f"(v));
    return r;
}
__device__ __forceinline__ unsigned long long packf2(float2 v) {
    unsigned long long r;
    asm("mov.b64 %0, {%1, %2};" : "=l"(r) : "f"(v.x), "f"(v.y));
    return r;
}
__device__ __forceinline__ float2 unpack2(unsigned long long a) {
    float2 r;
    asm("mov.b64 {%0, %1}, %2;" : "=f"(r.x), "=f"(r.y) : "l"(a));
    return r;
}
__device__ __forceinline__ float softplus_f(float x) {
    return fmaxf(x, 0.f) + log1pf(expf(-fabsf(x)));
}
__device__ __forceinline__ uint32_t s2u(const void* p) {
    uint32_t a;
    asm("{ .reg .u64 t; cvta.to.shared.u64 t, %1; cvt.u32.u64 %0, t; }"
        : "=r"(a) : "l"(p));
    return a;
}
__device__ __forceinline__ void cpa16(uint32_t d, const void* s) {
    asm volatile("cp.async.cg.shared.global [%0], [%1], 16;" :: "r"(d), "l"(s));
}
#define CP_COMMIT() asm volatile("cp.async.commit_group;" ::: "memory")
#define CP_WAIT1()  asm volatile("cp.async.wait_group 1;" ::: "memory")
#define CP_WAIT0()  asm volatile("cp.async.wait_group 0;" ::: "memory")

// ---------------- prep: pack weights, fold city into bias ----------------
__global__ void prep_kernel(const float* __restrict__ w_route,
                            const float* __restrict__ b_route,
                            const float* __restrict__ w_noise,
                            const float* __restrict__ b_noise,
                            const float* __restrict__ city_emb,
                            const int*   __restrict__ city_index)
{
    int idx = blockIdx.x * blockDim.x + threadIdx.x;
    if (idx < LINP * NEXP) {
        int pf = idx >> 4, e = idx & 15;
        int g = pf + (pf >= 1024 ? 32 : 0);   // skip city rows [1024,1056)
        g_wpack[idx] = make_float2(w_route[g * 16 + e], w_noise[g * 16 + e]);
    }
    if (idx < NEXP) {
        int ci = city_index[0];
        float br = b_route[idx], bn = b_noise[idx];
        #pragma unroll
        for (int j = 0; j < 32; j++) {
            float cv = city_emb[ci * 32 + j];
            br = fmaf(cv, w_route[(1024 + j) * 16 + idx], br);
            bn = fmaf(cv, w_noise[(1024 + j) * 16 + idx], bn);
        }
        g_bias[idx] = make_float2(br, bn);
    }
}

// ---------------- main fused kernel ----------------
__global__ __launch_bounds__(TPB, 4)
void router_main(const float* __restrict__ mh,
                 const float* __restrict__ dt,
                 const float* __restrict__ dd,
                 const float* __restrict__ drg,
                 const float* __restrict__ dent,
                 const float* __restrict__ eps,
                 float* __restrict__ out,
                 int out_size)
{
    // sm: main phase = Xs[2][16][64] (2048 f) + Ws[2][16][16] float2 (1024 f)
    //     epilogue   = red[64][17] float2 (2176 f) overlay
    __shared__ __align__(16) float sm[3072];
    float*  Xs = sm;
    float2* Ws = reinterpret_cast<float2*>(sm + 2048);

    const int tid  = threadIdx.x;
    const int lane = tid & 31;
    const int w    = tid >> 5;      // warp id == K-quarter
    const int og   = lane >> 4;     // 0..1 : expert-pairs og*8 .. og*8+7
    const int tg   = lane & 15;     // tokens 4*tg .. 4*tg+3
    const int tb   = blockIdx.x * TOKBLK;

    // acc[token][pair]: (route_logit, noise_logit) packed f32x2
    unsigned long long acc[4][8];
    #pragma unroll
    for (int j = 0; j < 8; j++) {
        unsigned long long b = (w == 0)
            ? *reinterpret_cast<const unsigned long long*>(&g_bias[og * 8 + j])
            : 0ull;
        #pragma unroll
        for (int i = 0; i < 4; i++) acc[i][j] = b;
    }

    // loader mapping: lq = feature-quad (0..3), lt = token (0..31); tokens lt, lt+32
    const int lq = tid & 3;
    const int lt = tid >> 2;
    const int swzS = 8 * lq;       // s(f) = 8*((f>>2)&3), f = 4*lq+j -> f>>2 = lq

    float4 xr[2];

    auto prefetchX = [&](int c) {
        const float* src; int colbase, stride;
        if (c < 64)       { src = mh;   colbase = c * 16;         stride = 1024; }
        else if (c < 80)  { src = dt;   colbase = (c - 64) * 16;  stride = 256;  }
        else if (c < 96)  { src = dd;   colbase = (c - 80) * 16;  stride = 256;  }
        else if (c < 104) { src = drg;  colbase = (c - 96) * 16;  stride = 128;  }
        else              { src = dent; colbase = (c - 104) * 16; stride = 128;  }
        const float* g = src + (size_t)(tb + lt) * stride + colbase + 4 * lq;
        xr[0] = *reinterpret_cast<const float4*>(g);
        xr[1] = *reinterpret_cast<const float4*>(g + (size_t)32 * stride);
    };
    auto storeX = [&](int buf) {
        float* xb = Xs + buf * 1024;
        #pragma unroll
        for (int q = 0; q < 2; q++) {
            const int t0 = lt + 32 * q;
            const float* v = reinterpret_cast<const float*>(&xr[q]);
            #pragma unroll
            for (int j = 0; j < 4; j++)
                xb[(4 * lq + j) * 64 + (t0 ^ swzS)] = v[j];
        }
    };
    auto issueW = [&](int c, int buf) {
        const char* gw = (const char*)(g_wpack + (size_t)c * KC * NEXP);
        cpa16(s2u(Ws + buf * KC * NEXP) + tid * 16, gw + tid * 16);
    };

    issueW(0, 0); CP_COMMIT();
    prefetchX(0);

    for (int c = 0; c < NCHUNK; c++) {
        const int buf = c & 1;
        __syncthreads();                 // buf free (compute c-1 done block-wide)
        storeX(buf);
        if (c + 1 < NCHUNK) {
            issueW(c + 1, buf ^ 1); CP_COMMIT();
            prefetchX(c + 1);
            CP_WAIT1();                  // W group c complete
        } else {
            CP_WAIT0();
        }
        __syncthreads();                 // stores + W visible block-wide

        const float*  xb = Xs + buf * 1024;
        const float2* wb = Ws + buf * KC * NEXP;
        #pragma unroll
        for (int f8 = 0; f8 < 4; f8++) {
            const int f = w * 4 + f8;                  // f>>2 == w here
            const float4 xv = *reinterpret_cast<const float4*>(
                &xb[f * 64 + ((4 * tg) ^ (8 * w))]);
            const ulonglong2 w0v = *reinterpret_cast<const ulonglong2*>(&wb[f * 16 + og * 8 + 0]);
            const ulonglong2 w1v = *reinterpret_cast<const ulonglong2*>(&wb[f * 16 + og * 8 + 2]);
            const ulonglong2 w2v = *reinterpret_cast<const ulonglong2*>(&wb[f * 16 + og * 8 + 4]);
            const ulonglong2 w3v = *reinterpret_cast<const ulonglong2*>(&wb[f * 16 + og * 8 + 6]);
            unsigned long long xx;
            xx = pack2(xv.x);
            fma2(acc[0][0], xx, w0v.x); fma2(acc[0][1], xx, w0v.y);
            fma2(acc[0][2], xx, w1v.x); fma2(acc[0][3], xx, w1v.y);
            fma2(acc[0][4], xx, w2v.x); fma2(acc[0][5], xx, w2v.y);
            fma2(acc[0][6], xx, w3v.x); fma2(acc[0][7], xx, w3v.y);
            xx = pack2(xv.y);
            fma2(acc[1][0], xx, w0v.x); fma2(acc[1][1], xx, w0v.y);
            fma2(acc[1][2], xx, w1v.x); fma2(acc[1][3], xx, w1v.y);
            fma2(acc[1][4], xx, w2v.x); fma2(acc[1][5], xx, w2v.y);
            fma2(acc[1][6], xx, w3v.x); fma2(acc[1][7], xx, w3v.y);
            xx = pack2(xv.z);
            fma2(acc[2][0], xx, w0v.x); fma2(acc[2][1], xx, w0v.y);
            fma2(acc[2][2], xx, w1v.x); fma2(acc[2][3], xx, w1v.y);
            fma2(acc[2][4], xx, w2v.x); fma2(acc[2][5], xx, w2v.y);
            fma2(acc[2][6], xx, w3v.x); fma2(acc[2][7], xx, w3v.y);
            xx = pack2(xv.w);
            fma2(acc[3][0], xx, w0v.x); fma2(acc[3][1], xx, w0v.y);
            fma2(acc[3][2], xx, w1v.x); fma2(acc[3][3], xx, w1v.y);
            fma2(acc[3][4], xx, w2v.x); fma2(acc[3][5], xx, w2v.y);
            fma2(acc[3][6], xx, w3v.x); fma2(acc[3][7], xx, w3v.y);
        }
    }

    // ---------------- 4-way K-split reduction ----------------
    __syncthreads();
    float2* red = reinterpret_cast<float2*>(sm);   // [64][17]
    #pragma unroll
    for (int s = 1; s < 4; s++) {
        if (w == s) {
            #pragma unroll
            for (int i = 0; i < 4; i++)
                #pragma unroll
                for (int j = 0; j < 8; j++)
                    red[(4 * tg + i) * 17 + og * 8 + j] = unpack2(acc[i][j]);
        }
        __syncthreads();
        if (w == 0) {
            #pragma unroll
            for (int i = 0; i < 4; i++)
                #pragma unroll
                for (int j = 0; j < 8; j++) {
                    float2 r = red[(4 * tg + i) * 17 + og * 8 + j];
                    float2 a = unpack2(acc[i][j]);
                    a.x += r.x; a.y += r.y;
                    acc[i][j] = packf2(a);
                }
        }
        __syncthreads();
    }
    if (w == 0) {
        #pragma unroll
        for (int i = 0; i < 4; i++)
            #pragma unroll
            for (int j = 0; j < 8; j++)
                red[(4 * tg + i) * 17 + og * 8 + j] = unpack2(acc[i][j]);
    }
    __syncthreads();

    // ---------------- per-token epilogue (64 threads) ----------------
    if (tid < TOKBLK) {
        const int t = tb + tid;
        float nz[16];
        {
            float4 ev[4];
            const float4* ep = reinterpret_cast<const float4*>(eps + (size_t)t * 16);
            ev[0] = ep[0]; ev[1] = ep[1]; ev[2] = ep[2]; ev[3] = ep[3];
            const float* ef = reinterpret_cast<const float*>(ev);
            #pragma unroll
            for (int e = 0; e < 16; e++) {
                float2 l = red[tid * 17 + e];
                nz[e] = l.x + ef[e] * softplus_f(l.y);
            }
        }

        // dense softmax (gate1)
        float m = nz[0];
        #pragma unroll
        for (int e = 1; e < 16; e++) m = fmaxf(m, nz[e]);
        float ex[16], ssum = 0.f;
        #pragma unroll
        for (int e = 0; e < 16; e++) { ex[e] = expf(nz[e] - m); ssum += ex[e]; }
        float inv = 1.f / ssum;

        // top-2 (first-occurrence ties, matches lax.top_k)
        int i1 = 0; float v1 = nz[0];
        #pragma unroll
        for (int e = 1; e < 16; e++) if (nz[e] > v1) { v1 = nz[e]; i1 = e; }
        int i2 = -1; float v2 = -INFINITY;
        #pragma unroll
        for (int e = 0; e < 16; e++) if (e != i1 && nz[e] > v2) { v2 = nz[e]; i2 = e; }

        float t2 = expf(v2 - v1);
        float r1 = 1.f / (1.f + t2);
        float r2 = t2 * r1;

        {
            float ro[16];
            #pragma unroll
            for (int e = 0; e < 16; e++)
                ro[e] = (e == i1) ? r1 : ((e == i2) ? r2 : 0.f);
            float4* op = reinterpret_cast<float4*>(out + (size_t)t * 16);
            op[0] = make_float4(ro[0],  ro[1],  ro[2],  ro[3]);
            op[1] = make_float4(ro[4],  ro[5],  ro[6],  ro[7]);
            op[2] = make_float4(ro[8],  ro[9],  ro[10], ro[11]);
            op[3] = make_float4(ro[12], ro[13], ro[14], ro[15]);
        }
        if (out_size >= IDX_OFF + NTOK * 2) {
            float2* ip = reinterpret_cast<float2*>(out + IDX_OFF + (size_t)t * 2);
            ip[0] = make_float2((float)i1, (float)i2);
        }
        if (out_size >= G1_OFF + NTOK * NEXP) {
            float g[16];
            #pragma unroll
            for (int e = 0; e < 16; e++) g[e] = ex[e] * inv;
            float4* gp = reinterpret_cast<float4*>(out + G1_OFF + (size_t)t * 16);
            gp[0] = make_float4(g[0],  g[1],  g[2],  g[3]);
            gp[1] = make_float4(g[4],  g[5],  g[6],  g[7]);
            gp[2] = make_float4(g[8],  g[9],  g[10], g[11]);
            gp[3] = make_float4(g[12], g[13], g[14], g[15]);
        }
    }
}

// ---------------- launch ----------------
extern "C" void kernel_launch(void* const* d_in, const int* in_sizes, int n_in,
                              void* d_out, int out_size)
{
    const float* mh      = (const float*)d_in[0];
    const float* dt      = (const float*)d_in[1];
    const float* dd      = (const float*)d_in[2];
    const float* drg     = (const float*)d_in[3];
    const float* dent    = (const float*)d_in[4];
    const float* city    = (const float*)d_in[5];
    const float* w_route = (const float*)d_in[6];
    const float* b_route = (const float*)d_in[7];
    const float* w_noise = (const float*)d_in[8];
    const float* b_noise = (const float*)d_in[9];
    const float* eps     = (const float*)d_in[10];
    const int*   ci      = (const int*)d_in[11];

    prep_kernel<<<(LINP * NEXP + 255) / 256, 256>>>(w_route, b_route,
                                                    w_noise, b_noise, city, ci);
    router_main<<<NBLK, TPB>>>(mh, dt, dd, drg, dent, eps,
                               (float*)d_out, out_size);
}